// round 6
// baseline (speedup 1.0000x reference)
#include <cuda_runtime.h>
#include <cuda_fp16.h>
#include <cstdint>

#define PADK 136           // halfs per smem row (128 + 8 pad) -> conflict-free LDSM
#define FULLMASK 0xffffffffu

// Scratch: per-node transformed features, fp16.
__device__ __half g_Y[(size_t)50000 * 256];
__device__ int g_idx64;

// ---------------------------------------------------------------------------
__device__ __forceinline__ unsigned sptr(const void* p) {
    return (unsigned)__cvta_generic_to_shared(p);
}
__device__ __forceinline__ void ldsm4(unsigned a, unsigned& r0, unsigned& r1,
                                      unsigned& r2, unsigned& r3) {
    asm volatile("ldmatrix.sync.aligned.m8n8.x4.shared.b16 {%0,%1,%2,%3}, [%4];\n"
                 : "=r"(r0), "=r"(r1), "=r"(r2), "=r"(r3) : "r"(a));
}
__device__ __forceinline__ void mma16816(float* c, unsigned a0, unsigned a1,
                                         unsigned a2, unsigned a3,
                                         unsigned b0, unsigned b1) {
    asm volatile(
        "mma.sync.aligned.m16n8k16.row.col.f32.f16.f16.f32 "
        "{%0,%1,%2,%3}, {%4,%5,%6,%7}, {%8,%9}, {%0,%1,%2,%3};\n"
        : "+f"(c[0]), "+f"(c[1]), "+f"(c[2]), "+f"(c[3])
        : "r"(a0), "r"(a1), "r"(a2), "r"(a3), "r"(b0), "r"(b1));
}

// ---------------------------------------------------------------------------
// Warp-level 32x64x128 GEMM (shared by both kernels).
// ---------------------------------------------------------------------------
__device__ __forceinline__ void warp_mma_32x64(const __half* Aw, const __half* Bw,
                                               float acc[2][8][4], int lane) {
    unsigned a_addr = sptr(Aw + (size_t)(lane & 15) * PADK + ((lane & 16) ? 8 : 0));
    unsigned b_addr = sptr(Bw + (size_t)((lane & 7) + ((lane & 16) ? 8 : 0)) * PADK
                              + ((lane & 8) ? 8 : 0));
    #pragma unroll
    for (int k0 = 0; k0 < 128; k0 += 16) {
        unsigned a0[4], a1[4];
        ldsm4(a_addr + k0 * 2, a0[0], a0[1], a0[2], a0[3]);
        ldsm4(a_addr + 16 * PADK * 2 + k0 * 2, a1[0], a1[1], a1[2], a1[3]);
        #pragma unroll
        for (int np = 0; np < 4; np++) {
            unsigned b0, b1, b2, b3;
            ldsm4(b_addr + (unsigned)(np * 16 * PADK * 2) + k0 * 2, b0, b1, b2, b3);
            mma16816(acc[0][2 * np],     a0[0], a0[1], a0[2], a0[3], b0, b1);
            mma16816(acc[0][2 * np + 1], a0[0], a0[1], a0[2], a0[3], b2, b3);
            mma16816(acc[1][2 * np],     a1[0], a1[1], a1[2], a1[3], b0, b1);
            mma16816(acc[1][2 * np + 1], a1[0], a1[1], a1[2], a1[3], b2, b3);
        }
    }
}

// ---------------------------------------------------------------------------
// Node kernel (persistent, block 512, 1 CTA/SM) — unchanged from R4.
// ---------------------------------------------------------------------------
__global__ __launch_bounds__(512, 1)
void node_gemm_kernel(const float* __restrict__ x,
                      const float* __restrict__ W1,
                      const void* __restrict__ ei,
                      int n_nodes) {
    extern __shared__ __half smem[];
    __half* As0 = smem;
    __half* As1 = smem + 128 * PADK;
    __half* Ws  = smem + 2 * 128 * PADK;   // [256 out-cols][PADK k]

    const int tid = threadIdx.x;

    if (blockIdx.x == 0 && tid < 32) {
        const unsigned* w = (const unsigned*)ei;
        unsigned v = w[2 * tid + 1] | w[2 * (tid + 32) + 1];
        int any_nz = __any_sync(FULLMASK, v != 0u);
        if (tid == 0) g_idx64 = any_nz ? 0 : 1;
    }

    for (int i = tid; i < 256 * 128; i += 512) {
        int c = i & 255, k = i >> 8;
        Ws[(size_t)c * PADK + k] =
            __float2half(W1[(size_t)(k + ((c >> 7) << 7)) * 128 + (c & 127)]);
    }

    const int warp = tid >> 5, lane = tid & 31;
    const int wm = warp & 3, wn = warp >> 2;   // 4M x 4N
    const int g = lane >> 2, t = lane & 3;
    const int n_tiles = (n_nodes + 127) >> 7;

    int li = 0;
    for (int tile = blockIdx.x; tile < n_tiles; tile += gridDim.x, li++) {
        __half* As = (li & 1) ? As1 : As0;
        const int row0 = tile << 7;

        for (int i = tid; i < 128 * 32; i += 512) {
            int r = i >> 5, c4 = i & 31;
            int gr = row0 + r;
            float4 v = make_float4(0.f, 0.f, 0.f, 0.f);
            if (gr < n_nodes) v = ((const float4*)x)[(size_t)gr * 32 + c4];
            __half* dst = As + (size_t)r * PADK + c4 * 4;
            dst[0] = __float2half(v.x); dst[1] = __float2half(v.y);
            dst[2] = __float2half(v.z); dst[3] = __float2half(v.w);
        }
        __syncthreads();

        float acc[2][8][4];
        #pragma unroll
        for (int mi = 0; mi < 2; mi++)
            #pragma unroll
            for (int n8 = 0; n8 < 8; n8++)
                acc[mi][n8][0] = acc[mi][n8][1] = acc[mi][n8][2] = acc[mi][n8][3] = 0.f;

        warp_mma_32x64(As + (size_t)(wm * 32) * PADK,
                       Ws + (size_t)(wn * 64) * PADK, acc, lane);

        #pragma unroll
        for (int mi = 0; mi < 2; mi++) {
            const int r0 = row0 + wm * 32 + mi * 16 + g;
            #pragma unroll
            for (int n8 = 0; n8 < 8; n8++) {
                int col = wn * 64 + n8 * 8 + 2 * t;
                if (r0 < n_nodes)
                    *(__half2*)(g_Y + (size_t)r0 * 256 + col) =
                        __floats2half2_rn(acc[mi][n8][0], acc[mi][n8][1]);
                if (r0 + 8 < n_nodes)
                    *(__half2*)(g_Y + (size_t)(r0 + 8) * 256 + col) =
                        __floats2half2_rn(acc[mi][n8][2], acc[mi][n8][3]);
            }
        }
    }
}

// ---------------------------------------------------------------------------
// Edge kernel (persistent, block 256, 3 CTAs/SM):
//   h = relu(Y[src,:128] + Y[dst,128:] + b1);  out = h @ W2 + b2
// Single H buffer (smem 68KB -> 3 CTAs/SM = 24 warps), reg-capped at 84.
// Next tile's edge indices prefetched before the epilogue.
// ---------------------------------------------------------------------------
__global__ __launch_bounds__(256, 3)
void edge_kernel(const void* __restrict__ edge_index,
                 const float* __restrict__ b1,
                 const float* __restrict__ W2,
                 const float* __restrict__ b2,
                 float* __restrict__ out,
                 int n_edges) {
    extern __shared__ __half smem[];
    __half* Hs = smem;                    // [128][PADK]
    __half* Ws = smem + 128 * PADK;       // [128 n][PADK k] = W2[k][n]

    const int tid = threadIdx.x;
    const int warp = tid >> 5, lane = tid & 31;
    const int wm = warp & 3, wn = warp >> 2;   // 4M x 2N
    const int g = lane >> 2, t = lane & 3;

    // Stage W2 once (transposed; coalesced on global side)
    for (int i = tid; i < 128 * 128; i += 256) {
        int k = i >> 7, n = i & 127;
        Ws[(size_t)n * PADK + k] = __float2half(W2[i]);  // W2[k*128+n]
    }

    const float4 b1v = *(const float4*)(b1 + lane * 4);

    const int is64 = g_idx64;
    const long long* idx64 = (const long long*)edge_index;
    const int*       idx32 = (const int*)edge_index;
    const int n_tiles = (n_edges + 127) >> 7;

    // index loader: lanes 0-15 = src of edge (lane&15), 16-31 = dst
    auto load_idx = [&](int tile) -> int {
        int myE = (tile << 7) + (warp << 4) + (lane & 15);
        if (myE >= n_edges) myE = n_edges - 1;
        size_t off = (lane < 16) ? (size_t)myE : (size_t)n_edges + (size_t)myE;
        return is64 ? (int)idx64[off] : idx32[off];
    };

    int tile = blockIdx.x;
    if (tile >= n_tiles) return;
    int vidx = load_idx(tile);
    __syncthreads();   // Ws staged

    while (true) {
        const int e0 = tile << 7;

        // ---- warp-cooperative gather (batched x4) -> Hs ----
        {
            __half* Hrow = Hs + (size_t)(warp << 4) * PADK + lane * 4;
            #pragma unroll
            for (int i = 0; i < 16; i += 4) {
                uint2 va[4], vd[4];
                #pragma unroll
                for (int j = 0; j < 4; j++) {
                    int s = __shfl_sync(FULLMASK, vidx, i + j);
                    int d = __shfl_sync(FULLMASK, vidx, 16 + i + j);
                    va[j] = *(const uint2*)(g_Y + (size_t)s * 256 + lane * 4);
                    vd[j] = *(const uint2*)(g_Y + (size_t)d * 256 + 128 + lane * 4);
                }
                #pragma unroll
                for (int j = 0; j < 4; j++) {
                    float2 fa0 = __half22float2(*(const __half2*)&va[j].x);
                    float2 fd0 = __half22float2(*(const __half2*)&vd[j].x);
                    float2 fa1 = __half22float2(*(const __half2*)&va[j].y);
                    float2 fd1 = __half22float2(*(const __half2*)&vd[j].y);
                    __half2 r0 = __floats2half2_rn(fmaxf(fa0.x + fd0.x + b1v.x, 0.f),
                                                   fmaxf(fa0.y + fd0.y + b1v.y, 0.f));
                    __half2 r1 = __floats2half2_rn(fmaxf(fa1.x + fd1.x + b1v.z, 0.f),
                                                   fmaxf(fa1.y + fd1.y + b1v.w, 0.f));
                    uint2 rv;
                    rv.x = *(const unsigned*)&r0;
                    rv.y = *(const unsigned*)&r1;
                    *(uint2*)(Hrow + (size_t)(i + j) * PADK) = rv;
                }
            }
        }
        __syncthreads();   // H complete

        // ---- 32x64 warp-tile GEMM ----
        float acc[2][8][4];
        #pragma unroll
        for (int mi = 0; mi < 2; mi++)
            #pragma unroll
            for (int n8 = 0; n8 < 8; n8++)
                acc[mi][n8][0] = acc[mi][n8][1] = acc[mi][n8][2] = acc[mi][n8][3] = 0.f;

        warp_mma_32x64(Hs + (size_t)(wm * 32) * PADK,
                       Ws + (size_t)(wn * 64) * PADK, acc, lane);

        // ---- prefetch next tile's indices (off critical path) ----
        const int next = tile + gridDim.x;
        const bool more = next < n_tiles;
        int vnext = more ? load_idx(next) : 0;

        // ---- epilogue: +b2 (via __ldg), store fp32 ----
        #pragma unroll
        for (int mi = 0; mi < 2; mi++) {
            const int r0 = e0 + wm * 32 + mi * 16 + g;
            #pragma unroll
            for (int n8 = 0; n8 < 8; n8++) {
                int col = wn * 64 + n8 * 8 + 2 * t;
                float bx = __ldg(b2 + col), by = __ldg(b2 + col + 1);
                if (r0 < n_edges)
                    *(float2*)(out + (size_t)r0 * 128 + col) =
                        make_float2(acc[mi][n8][0] + bx, acc[mi][n8][1] + by);
                if (r0 + 8 < n_edges)
                    *(float2*)(out + (size_t)(r0 + 8) * 128 + col) =
                        make_float2(acc[mi][n8][2] + bx, acc[mi][n8][3] + by);
            }
        }

        if (!more) break;
        __syncthreads();   // all warps done with Hs -> safe to re-gather
        tile = next; vidx = vnext;
    }
}

// ---------------------------------------------------------------------------
extern "C" void kernel_launch(void* const* d_in, const int* in_sizes, int n_in,
                              void* d_out, int out_size) {
    const float* x  = (const float*)d_in[0];
    const void*  ei = d_in[1];
    const float* W1 = (const float*)d_in[2];
    const float* b1 = (const float*)d_in[3];
    const float* W2 = (const float*)d_in[4];
    const float* b2 = (const float*)d_in[5];
    float* out = (float*)d_out;

    const int n_nodes = in_sizes[0] / 128;
    const int n_edges = in_sizes[1] / 2;

    const int node_smem = (2 * 128 + 256) * PADK * (int)sizeof(__half);  // 139264
    const int edge_smem = 2 * 128 * PADK * (int)sizeof(__half);          // 69632
    static bool attr_set = false;
    if (!attr_set) {
        cudaFuncSetAttribute(node_gemm_kernel,
                             cudaFuncAttributeMaxDynamicSharedMemorySize, node_smem);
        cudaFuncSetAttribute(edge_kernel,
                             cudaFuncAttributeMaxDynamicSharedMemorySize, edge_smem);
        attr_set = true;
    }

    const int node_tiles = (n_nodes + 127) / 128;
    int g1 = node_tiles < 148 ? node_tiles : 148;
    node_gemm_kernel<<<g1, 512, node_smem>>>(x, W1, ei, n_nodes);

    const int edge_tiles = (n_edges + 127) / 128;
    int g2 = edge_tiles < 444 ? edge_tiles : 444;
    edge_kernel<<<g2, 256, edge_smem>>>(ei, b1, W2, b2, out, n_edges);
}

// round 7
// speedup vs baseline: 1.5596x; 1.5596x over previous
#include <cuda_runtime.h>
#include <cuda_fp16.h>
#include <cstdint>

#define PADK 136           // halfs per smem row (128 + 8 pad) -> conflict-free LDSM
#define CPAD 136           // floats per C-stage row (conflict-free STS, fits buffer)
#define FULLMASK 0xffffffffu

// Scratch: per-node transformed features, fp16.
__device__ __half g_Y[(size_t)50000 * 256];
__device__ int g_idx64;

// ---------------------------------------------------------------------------
__device__ __forceinline__ unsigned sptr(const void* p) {
    return (unsigned)__cvta_generic_to_shared(p);
}
__device__ __forceinline__ void ldsm4(unsigned a, unsigned& r0, unsigned& r1,
                                      unsigned& r2, unsigned& r3) {
    asm volatile("ldmatrix.sync.aligned.m8n8.x4.shared.b16 {%0,%1,%2,%3}, [%4];\n"
                 : "=r"(r0), "=r"(r1), "=r"(r2), "=r"(r3) : "r"(a));
}
__device__ __forceinline__ void mma16816(float* c, unsigned a0, unsigned a1,
                                         unsigned a2, unsigned a3,
                                         unsigned b0, unsigned b1) {
    asm volatile(
        "mma.sync.aligned.m16n8k16.row.col.f32.f16.f16.f32 "
        "{%0,%1,%2,%3}, {%4,%5,%6,%7}, {%8,%9}, {%0,%1,%2,%3};\n"
        : "+f"(c[0]), "+f"(c[1]), "+f"(c[2]), "+f"(c[3])
        : "r"(a0), "r"(a1), "r"(a2), "r"(a3), "r"(b0), "r"(b1));
}

// ---------------------------------------------------------------------------
// Warp-level 32x64x128 GEMM.
// ---------------------------------------------------------------------------
__device__ __forceinline__ void warp_mma_32x64(const __half* Aw, const __half* Bw,
                                               float acc[2][8][4], int lane) {
    unsigned a_addr = sptr(Aw + (size_t)(lane & 15) * PADK + ((lane & 16) ? 8 : 0));
    unsigned b_addr = sptr(Bw + (size_t)((lane & 7) + ((lane & 16) ? 8 : 0)) * PADK
                              + ((lane & 8) ? 8 : 0));
    #pragma unroll
    for (int k0 = 0; k0 < 128; k0 += 16) {
        unsigned a0[4], a1[4];
        ldsm4(a_addr + k0 * 2, a0[0], a0[1], a0[2], a0[3]);
        ldsm4(a_addr + 16 * PADK * 2 + k0 * 2, a1[0], a1[1], a1[2], a1[3]);
        #pragma unroll
        for (int np = 0; np < 4; np++) {
            unsigned b0, b1, b2, b3;
            ldsm4(b_addr + (unsigned)(np * 16 * PADK * 2) + k0 * 2, b0, b1, b2, b3);
            mma16816(acc[0][2 * np],     a0[0], a0[1], a0[2], a0[3], b0, b1);
            mma16816(acc[0][2 * np + 1], a0[0], a0[1], a0[2], a0[3], b2, b3);
            mma16816(acc[1][2 * np],     a1[0], a1[1], a1[2], a1[3], b0, b1);
            mma16816(acc[1][2 * np + 1], a1[0], a1[1], a1[2], a1[3], b2, b3);
        }
    }
}

// ---------------------------------------------------------------------------
// Node kernel (persistent, block 512, 1 CTA/SM) — unchanged from R4.
// ---------------------------------------------------------------------------
__global__ __launch_bounds__(512, 1)
void node_gemm_kernel(const float* __restrict__ x,
                      const float* __restrict__ W1,
                      const void* __restrict__ ei,
                      int n_nodes) {
    extern __shared__ __half smem[];
    __half* As0 = smem;
    __half* As1 = smem + 128 * PADK;
    __half* Ws  = smem + 2 * 128 * PADK;   // [256 out-cols][PADK k]

    const int tid = threadIdx.x;

    if (blockIdx.x == 0 && tid < 32) {
        const unsigned* w = (const unsigned*)ei;
        unsigned v = w[2 * tid + 1] | w[2 * (tid + 32) + 1];
        int any_nz = __any_sync(FULLMASK, v != 0u);
        if (tid == 0) g_idx64 = any_nz ? 0 : 1;
    }

    for (int i = tid; i < 256 * 128; i += 512) {
        int c = i & 255, k = i >> 8;
        Ws[(size_t)c * PADK + k] =
            __float2half(W1[(size_t)(k + ((c >> 7) << 7)) * 128 + (c & 127)]);
    }

    const int warp = tid >> 5, lane = tid & 31;
    const int wm = warp & 3, wn = warp >> 2;   // 4M x 4N
    const int g = lane >> 2, t = lane & 3;
    const int n_tiles = (n_nodes + 127) >> 7;

    int li = 0;
    for (int tile = blockIdx.x; tile < n_tiles; tile += gridDim.x, li++) {
        __half* As = (li & 1) ? As1 : As0;
        const int row0 = tile << 7;

        for (int i = tid; i < 128 * 32; i += 512) {
            int r = i >> 5, c4 = i & 31;
            int gr = row0 + r;
            float4 v = make_float4(0.f, 0.f, 0.f, 0.f);
            if (gr < n_nodes) v = ((const float4*)x)[(size_t)gr * 32 + c4];
            __half* dst = As + (size_t)r * PADK + c4 * 4;
            dst[0] = __float2half(v.x); dst[1] = __float2half(v.y);
            dst[2] = __float2half(v.z); dst[3] = __float2half(v.w);
        }
        __syncthreads();

        float acc[2][8][4];
        #pragma unroll
        for (int mi = 0; mi < 2; mi++)
            #pragma unroll
            for (int n8 = 0; n8 < 8; n8++)
                acc[mi][n8][0] = acc[mi][n8][1] = acc[mi][n8][2] = acc[mi][n8][3] = 0.f;

        warp_mma_32x64(As + (size_t)(wm * 32) * PADK,
                       Ws + (size_t)(wn * 64) * PADK, acc, lane);

        #pragma unroll
        for (int mi = 0; mi < 2; mi++) {
            const int r0 = row0 + wm * 32 + mi * 16 + g;
            #pragma unroll
            for (int n8 = 0; n8 < 8; n8++) {
                int col = wn * 64 + n8 * 8 + 2 * t;
                if (r0 < n_nodes)
                    *(__half2*)(g_Y + (size_t)r0 * 256 + col) =
                        __floats2half2_rn(acc[mi][n8][0], acc[mi][n8][1]);
                if (r0 + 8 < n_nodes)
                    *(__half2*)(g_Y + (size_t)(r0 + 8) * 256 + col) =
                        __floats2half2_rn(acc[mi][n8][2], acc[mi][n8][3]);
            }
        }
    }
}

// ---------------------------------------------------------------------------
// Edge kernel (persistent, block 256, 2 CTAs/SM) — R4 base + staged epilogue:
//   h = relu(Y[src,:128] + Y[dst,128:] + b1);  out = h @ W2 + b2
// C (+b2) staged through the idle H ping-pong buffer, then written with
// full-row coalesced STG.128 (one warp per 512B output row).
// ---------------------------------------------------------------------------
__global__ __launch_bounds__(256, 2)
void edge_kernel(const void* __restrict__ edge_index,
                 const float* __restrict__ b1,
                 const float* __restrict__ W2,
                 const float* __restrict__ b2,
                 float* __restrict__ out,
                 int n_edges) {
    extern __shared__ char dsm[];
    __half* HsA[2] = { (__half*)dsm, (__half*)(dsm + 34816) };
    __half* Ws = (__half*)(dsm + 69632);   // [128 n][PADK k] = W2[k][n]

    const int tid = threadIdx.x;
    const int warp = tid >> 5, lane = tid & 31;
    const int wm = warp & 3, wn = warp >> 2;   // 4M x 2N
    const int g = lane >> 2, t = lane & 3;

    // Stage W2 once (transposed; coalesced on global side)
    for (int i = tid; i < 128 * 128; i += 256) {
        int k = i >> 7, n = i & 127;
        Ws[(size_t)n * PADK + k] = __float2half(W2[i]);  // W2[k*128+n]
    }

    // Per-lane constants
    const float4 b1v = *(const float4*)(b1 + lane * 4);
    float2 breg[8];
    #pragma unroll
    for (int n8 = 0; n8 < 8; n8++)
        breg[n8] = *(const float2*)(b2 + wn * 64 + n8 * 8 + 2 * t);

    const int is64 = g_idx64;
    const long long* idx64 = (const long long*)edge_index;
    const int*       idx32 = (const int*)edge_index;
    const int n_tiles = (n_edges + 127) >> 7;

    auto load_idx = [&](int tl) -> int {
        int myE = (tl << 7) + (warp << 4) + (lane & 15);
        if (myE >= n_edges) myE = n_edges - 1;
        size_t off = (lane < 16) ? (size_t)myE : (size_t)n_edges + (size_t)myE;
        return is64 ? (int)idx64[off] : idx32[off];
    };

    int tile = blockIdx.x;
    if (tile >= n_tiles) return;
    int vidx = load_idx(tile);
    __syncthreads();   // Ws staged

    int li = 0;
    while (true) {
        __half* Hs = HsA[li & 1];
        float*  Cs = (float*)HsA[1 - (li & 1)];   // idle buffer -> fp32 stage
        const int e0 = tile << 7;

        // ---- warp-cooperative gather (batched x4) -> Hs ----
        {
            __half* Hrow = Hs + (size_t)(warp << 4) * PADK + lane * 4;
            #pragma unroll
            for (int i = 0; i < 16; i += 4) {
                uint2 va[4], vd[4];
                #pragma unroll
                for (int j = 0; j < 4; j++) {
                    int s = __shfl_sync(FULLMASK, vidx, i + j);
                    int d = __shfl_sync(FULLMASK, vidx, 16 + i + j);
                    va[j] = *(const uint2*)(g_Y + (size_t)s * 256 + lane * 4);
                    vd[j] = *(const uint2*)(g_Y + (size_t)d * 256 + 128 + lane * 4);
                }
                #pragma unroll
                for (int j = 0; j < 4; j++) {
                    float2 fa0 = __half22float2(*(const __half2*)&va[j].x);
                    float2 fd0 = __half22float2(*(const __half2*)&vd[j].x);
                    float2 fa1 = __half22float2(*(const __half2*)&va[j].y);
                    float2 fd1 = __half22float2(*(const __half2*)&vd[j].y);
                    __half2 r0 = __floats2half2_rn(fmaxf(fa0.x + fd0.x + b1v.x, 0.f),
                                                   fmaxf(fa0.y + fd0.y + b1v.y, 0.f));
                    __half2 r1 = __floats2half2_rn(fmaxf(fa1.x + fd1.x + b1v.z, 0.f),
                                                   fmaxf(fa1.y + fd1.y + b1v.w, 0.f));
                    uint2 rv;
                    rv.x = *(const unsigned*)&r0;
                    rv.y = *(const unsigned*)&r1;
                    *(uint2*)(Hrow + (size_t)(i + j) * PADK) = rv;
                }
            }
        }
        __syncthreads();   // (A) H ready; prior tile's readout complete

        // ---- 32x64 warp-tile GEMM ----
        float acc[2][8][4];
        #pragma unroll
        for (int mi = 0; mi < 2; mi++)
            #pragma unroll
            for (int n8 = 0; n8 < 8; n8++)
                acc[mi][n8][0] = acc[mi][n8][1] = acc[mi][n8][2] = acc[mi][n8][3] = 0.f;

        warp_mma_32x64(Hs + (size_t)(wm * 32) * PADK,
                       Ws + (size_t)(wn * 64) * PADK, acc, lane);

        // ---- prefetch next tile's indices (off critical path) ----
        const int next = tile + gridDim.x;
        const bool more = next < n_tiles;
        int vnext = more ? load_idx(next) : 0;

        // ---- staged epilogue: 2 chunks of 64 rows ----
        #pragma unroll
        for (int mi = 0; mi < 2; mi++) {
            // STS: acc + b2 -> Cs[local row][col], local row = wm*16 + g (+8)
            const int rloc = wm * 16 + g;
            #pragma unroll
            for (int n8 = 0; n8 < 8; n8++) {
                int col = wn * 64 + n8 * 8 + 2 * t;
                *(float2*)(Cs + (size_t)rloc * CPAD + col) =
                    make_float2(acc[mi][n8][0] + breg[n8].x,
                                acc[mi][n8][1] + breg[n8].y);
                *(float2*)(Cs + (size_t)(rloc + 8) * CPAD + col) =
                    make_float2(acc[mi][n8][2] + breg[n8].x,
                                acc[mi][n8][3] + breg[n8].y);
            }
            __syncthreads();   // (B) chunk staged

            // Readout: one warp per row per pass, full 512B row STG.128
            #pragma unroll
            for (int pass = 0; pass < 8; pass++) {
                const int rl = pass * 8 + warp;               // 0..63
                const int grow = e0 + ((rl >> 4) << 5) + mi * 16 + (rl & 15);
                if (grow < n_edges) {
                    float4 v = *(const float4*)(Cs + (size_t)rl * CPAD + lane * 4);
                    *(float4*)(out + (size_t)grow * 128 + lane * 4) = v;
                }
            }
            __syncthreads();   // (C) chunk consumed
        }

        if (!more) break;
        tile = next; vidx = vnext; li++;
    }
}

// ---------------------------------------------------------------------------
extern "C" void kernel_launch(void* const* d_in, const int* in_sizes, int n_in,
                              void* d_out, int out_size) {
    const float* x  = (const float*)d_in[0];
    const void*  ei = d_in[1];
    const float* W1 = (const float*)d_in[2];
    const float* b1 = (const float*)d_in[3];
    const float* W2 = (const float*)d_in[4];
    const float* b2 = (const float*)d_in[5];
    float* out = (float*)d_out;

    const int n_nodes = in_sizes[0] / 128;
    const int n_edges = in_sizes[1] / 2;

    const int node_smem = (2 * 128 + 256) * PADK * (int)sizeof(__half);  // 139264
    const int edge_smem = 3 * 128 * PADK * (int)sizeof(__half);          // 104448
    static bool attr_set = false;
    if (!attr_set) {
        cudaFuncSetAttribute(node_gemm_kernel,
                             cudaFuncAttributeMaxDynamicSharedMemorySize, node_smem);
        cudaFuncSetAttribute(edge_kernel,
                             cudaFuncAttributeMaxDynamicSharedMemorySize, edge_smem);
        attr_set = true;
    }

    const int node_tiles = (n_nodes + 127) / 128;
    int g1 = node_tiles < 148 ? node_tiles : 148;
    node_gemm_kernel<<<g1, 512, node_smem>>>(x, W1, ei, n_nodes);

    const int edge_tiles = (n_edges + 127) / 128;
    int g2 = edge_tiles < 296 ? edge_tiles : 296;
    edge_kernel<<<g2, 256, edge_smem>>>(ei, b1, W2, b2, out, n_edges);
}